// round 15
// baseline (speedup 1.0000x reference)
#include <cuda_runtime.h>
#include <cuda.h>
#include <cuda_bf16.h>
#include <math.h>
#include <stdint.h>

// ----------------------------------------------------------------------------
// RelNet forward, tcgen05 sm_103a, bf16 hi/lo split GEMMs.
// cta_group::2 (cluster=2): pair tile M=256 x N=256, B split N/2 per CTA.
// 4-stage TMA ring, per-CTA SMEM reads cut 3x vs cg1.
// ----------------------------------------------------------------------------

#if defined(__CUDA_ARCH__) && (defined(__CUDA_ARCH_FEAT_SM103_ALL) || \
    defined(__CUDA_ARCH_FEAT_SM100_ALL) || defined(__CUDA_ARCH_FEAT_SM101_ALL))
#define TC_OK 1
#else
#define TC_OK 0
#endif

#define NB   64
#define HW   64
#define FDIM 66
#define G    512
#define E    256
#define MROWS (NB * HW * HW)   // 262144

#define BMP 256                // rows per cluster pair
#define BMC 128                // rows per CTA
#define BN  256
#define BK  32
#define TITER (G / BK)         // 16
#define NSTAGE 4
#define THREADS 512
#define NPAIRS (MROWS / BMP)   // 1024
#define NCTAX  (NPAIRS * 2)    // 2048

// SMEM: ctrl + 4 stages x 32KB (Ahi8K|Alo8K|Bhi8K|Blo8K per CTA)
#define S_TMEM_O  0
#define S_FULL(b) (8   + (b) * 8)
#define S_FREE(b) (40  + (b) * 8)
#define S_R1RD(b) (72  + (b) * 8)
#define S_DONE    104
#define S_BIAS    128
#define STAGE_SZ  32768
#define ST_A_HI(b) (4096 + (b) * STAGE_SZ)
#define ST_A_LO(b) (ST_A_HI(b) + 8192)
#define ST_B_HI(b) (ST_A_HI(b) + 16384)
#define ST_B_LO(b) (ST_A_HI(b) + 24576)
#define SMEM_SZ    (4096 + NSTAGE * STAGE_SZ)   // 135168

// idesc cg2 kind::f16: dtype=F32, a/b=BF16, N=256, M=256
#define MMA_IDESC ((1u<<4)|(1u<<7)|(1u<<10)|((BN/8)<<17)|((BMP/16)<<24))

// SW64 K-major descriptor (layout=4, version=1, SBO=32, LBO=1); 64B rows
#define SMEM_DESC_BASE_SW64 \
    ((uint64_t(4)<<61)|(uint64_t(1)<<46)|(uint64_t(32)<<32)|(uint64_t(1)<<16))
#define MAKE_DESC64(a) (SMEM_DESC_BASE_SW64 | ((uint64_t)((a) >> 4) & 0x3FFF))
#define SWZ64(o) ((o) ^ (((o) >> 3) & 0x30))

// ---------------- device scratch (separate hi/lo planes) ----------------
__device__ unsigned short g_h2h[(size_t)MROWS * G], g_h2l[(size_t)MROWS * G];
__device__ unsigned short g_h3h[(size_t)MROWS * G], g_h3l[(size_t)MROWS * G];
__device__ float          g_Ai[(size_t)NB * HW * G];
__device__ float          g_Bj[(size_t)NB * HW * G];
__device__ float          g_Cq[NB * G];
__device__ float          g_part[(size_t)NCTAX * G];    // 2048 x 512
__device__ float          g_ctx[NB * G];
__device__ unsigned short g_w2h[G * G], g_w2l[G * G];
__device__ unsigned short g_w3h[G * G], g_w3l[G * G];
__device__ unsigned short g_w4h[G * G], g_w4l[G * G];

// ---------------- generic helpers ----------------
__device__ __forceinline__ void split2t(float v0, float v1, unsigned &hi, unsigned &lo) {
    unsigned u0 = __float_as_uint(v0), u1 = __float_as_uint(v1);
    hi = __byte_perm(u0, u1, 0x7632);
    float l0 = v0 - __uint_as_float(u0 & 0xFFFF0000u);
    float l1 = v1 - __uint_as_float(u1 & 0xFFFF0000u);
    lo = __byte_perm(__float_as_uint(l0), __float_as_uint(l1), 0x7632);
}
__device__ __forceinline__ float us2f(unsigned short u) {
    return __bfloat162float(__ushort_as_bfloat16(u));
}

#if TC_OK
// ---------------- tcgen05 / async PTX helpers (sm_103a only) ----------------
__device__ __forceinline__ uint32_t smem_u32(const void* p) {
    uint32_t a;
    asm("{ .reg .u64 t; cvta.to.shared.u64 t, %1; cvt.u32.u64 %0, t; }"
        : "=r"(a) : "l"(p));
    return a;
}
__device__ __forceinline__ uint32_t elect_one() {
    uint32_t p;
    asm volatile("{ .reg .pred p; elect.sync _|p, 0xFFFFFFFF; selp.b32 %0,1,0,p; }"
                 : "=r"(p));
    return p;
}
__device__ __forceinline__ uint32_t ctarank() {
    uint32_t r;
    asm("mov.u32 %0, %%cluster_ctarank;" : "=r"(r));
    return r;
}
__device__ __forceinline__ void mma_bf16_ss_cg2(uint32_t d, uint64_t ad, uint64_t bd,
                                                uint32_t idesc, uint32_t en) {
    asm volatile(
        "{\n\t.reg .pred p;\n\tsetp.ne.u32 p, %4, 0;\n\t"
        "tcgen05.mma.cta_group::2.kind::f16 [%0], %1, %2, %3, "
        "{%5,%5,%5,%5,%5,%5,%5,%5}, p;\n\t}"
        :: "r"(d), "l"(ad), "l"(bd), "r"(idesc), "r"(en), "r"(0u) : "memory");
}
#define TC_ALLOC2(sp, n)  asm volatile("tcgen05.alloc.cta_group::2.sync.aligned.shared::cta.b32 [%0], %1;" :: "r"(sp), "r"(n) : "memory")
#define TC_RELINQ2()      asm volatile("tcgen05.relinquish_alloc_permit.cta_group::2.sync.aligned;")
#define TC_DEALLOC2(t, n) asm volatile("tcgen05.dealloc.cta_group::2.sync.aligned.b32 %0, %1;" :: "r"(t), "r"(n))
#define TC_COMMIT_MC2(mb, m) asm volatile("tcgen05.commit.cta_group::2.mbarrier::arrive::one.shared::cluster.multicast::cluster.b64 [%0], %1;" :: "r"(mb), "h"((uint16_t)(m)) : "memory")
#define TC_FENCE_AFTER() asm volatile("tcgen05.fence::after_thread_sync;" ::: "memory")
#define TC_WAIT_LD()     asm volatile("tcgen05.wait::ld.sync.aligned;" ::: "memory")
#define FENCE_ASYNC()    asm volatile("fence.proxy.async;" ::: "memory")
#define MBAR_INIT(mb, c) asm volatile("mbarrier.init.shared.b64 [%0], %1;" :: "r"(mb), "r"(c) : "memory")
#define MBAR_INVAL(mb)   asm volatile("mbarrier.inval.shared.b64 [%0];" :: "r"(mb) : "memory")
#define MBAR_ARRIVE(mb)  asm volatile("mbarrier.arrive.release.cta.shared::cta.b64 _, [%0];" :: "r"(mb) : "memory")
#define MBAR_ARRIVE_LEADER(mb) \
    asm volatile("{\n\t.reg .b32 la;\n\tand.b32 la, %0, 0xFEFFFFFF;\n\t" \
                 "mbarrier.arrive.release.cluster.shared::cluster.b64 _, [la];\n\t}" \
                 :: "r"(mb) : "memory")
#define MBAR_EXPECT_TX(mb, n) asm volatile("mbarrier.arrive.expect_tx.shared.b64 _, [%0], %1;" :: "r"(mb), "r"((uint32_t)(n)) : "memory")
#define TMA2D(dst, map, x, y, mb) \
    asm volatile("cp.async.bulk.tensor.2d.shared::cta.global.tile.mbarrier::complete_tx::bytes " \
                 "[%0], [%1, {%2, %3}], [%4];" \
                 :: "r"(dst), "l"(map), "r"(x), "r"(y), "r"(mb) : "memory")
#define CLUSTER_SYNC() do { \
    asm volatile("barrier.cluster.arrive.aligned;" ::: "memory"); \
    asm volatile("barrier.cluster.wait.aligned;" ::: "memory"); } while (0)

__device__ __forceinline__ void mbar_wait(uint32_t mb, uint32_t parity) {
    asm volatile(
        "{\n\t.reg .pred P;\n\t"
        "WL_%=:\n\t"
        "mbarrier.try_wait.parity.acquire.cta.shared::cta.b64 P, [%0], %1, 0x989680;\n\t"
        "@P bra.uni WD_%=;\n\t"
        "bra.uni WL_%=;\n\t"
        "WD_%=:\n\t}"
        :: "r"(mb), "r"(parity) : "memory");
}
__device__ __forceinline__ void mbar_wait_clu(uint32_t mb, uint32_t parity) {
    asm volatile(
        "{\n\t.reg .pred P;\n\t"
        "WL_%=:\n\t"
        "mbarrier.try_wait.parity.acquire.cluster.shared::cta.b64 P, [%0], %1, 0x989680;\n\t"
        "@P bra.uni WD_%=;\n\t"
        "bra.uni WL_%=;\n\t"
        "WD_%=:\n\t}"
        :: "r"(mb), "r"(parity) : "memory");
}
#define TC_LD_X32(r, a) \
    asm volatile("tcgen05.ld.sync.aligned.32x32b.x32.b32 " \
        "{%0,%1,%2,%3,%4,%5,%6,%7,%8,%9,%10,%11,%12,%13,%14,%15," \
        "%16,%17,%18,%19,%20,%21,%22,%23,%24,%25,%26,%27,%28,%29,%30,%31}, [%32];" \
        : "=r"((r)[0]),"=r"((r)[1]),"=r"((r)[2]),"=r"((r)[3]), \
          "=r"((r)[4]),"=r"((r)[5]),"=r"((r)[6]),"=r"((r)[7]), \
          "=r"((r)[8]),"=r"((r)[9]),"=r"((r)[10]),"=r"((r)[11]), \
          "=r"((r)[12]),"=r"((r)[13]),"=r"((r)[14]),"=r"((r)[15]), \
          "=r"((r)[16]),"=r"((r)[17]),"=r"((r)[18]),"=r"((r)[19]), \
          "=r"((r)[20]),"=r"((r)[21]),"=r"((r)[22]),"=r"((r)[23]), \
          "=r"((r)[24]),"=r"((r)[25]),"=r"((r)[26]),"=r"((r)[27]), \
          "=r"((r)[28]),"=r"((r)[29]),"=r"((r)[30]),"=r"((r)[31]) \
        : "r"(a))
#endif  // TC_OK

// ---- K1: Ai = feat_i @ W1a, Bj = feat_j @ W1b (8 positions per block) ------
__global__ void k_ab(const float* __restrict__ img, const float* __restrict__ w1) {
    int n = blockIdx.x, pg = blockIdx.y;     // 64 x 8
    int tid = threadIdx.x;                   // 512
    __shared__ float f[8][FDIM];
    if (tid < 64) {
        int c = tid;
        #pragma unroll
        for (int p8 = 0; p8 < 8; ++p8)
            f[p8][c] = img[((size_t)n * 64 + c) * 64 + pg * 8 + p8];
    } else if (tid < 72) {
        int p8 = tid - 64, p = pg * 8 + p8;
        f[p8][64] = (float)(p >> 3);
        f[p8][65] = (float)(p & 7);
    }
    __syncthreads();
    float a[8] = {0,0,0,0,0,0,0,0}, b[8] = {0,0,0,0,0,0,0,0};
    #pragma unroll 2
    for (int c = 0; c < FDIM; ++c) {
        float wa = w1[(size_t)c * G + tid];
        float wb = w1[(size_t)(c + FDIM) * G + tid];
        #pragma unroll
        for (int p8 = 0; p8 < 8; ++p8) {
            a[p8] = fmaf(f[p8][c], wa, a[p8]);
            b[p8] = fmaf(f[p8][c], wb, b[p8]);
        }
    }
    #pragma unroll
    for (int p8 = 0; p8 < 8; ++p8) {
        int row = n * 64 + pg * 8 + p8;
        g_Ai[(size_t)row * G + tid] = a[p8];
        g_Bj[(size_t)row * G + tid] = b[p8];
    }
}

// ---- K2: Cq = ques @ W1c + b1 ----------------------------------------------
__global__ void k_cq(const float* __restrict__ ques, const float* __restrict__ w1,
                     const float* __restrict__ b1) {
    int n = blockIdx.x, tid = threadIdx.x;    // 512 threads
    __shared__ float q[E];
    if (tid < E) q[tid] = ques[n * E + tid];
    __syncthreads();
    float s0 = b1[tid], s1 = 0.f;
    #pragma unroll 8
    for (int e = 0; e < E; e += 2) {
        s0 = fmaf(q[e],     w1[(size_t)(2 * FDIM + e) * G + tid], s0);
        s1 = fmaf(q[e + 1], w1[(size_t)(2 * FDIM + e + 1) * G + tid], s1);
    }
    g_Cq[n * G + tid] = s0 + s1;
}

// ---- weight prep: transpose + bf16 hi/lo split (RN, done once) -------------
__global__ void k_wprep3(const float* __restrict__ W2, const float* __restrict__ W3,
                         const float* __restrict__ W4,
                         unsigned short* __restrict__ h2, unsigned short* __restrict__ l2,
                         unsigned short* __restrict__ h3, unsigned short* __restrict__ l3,
                         unsigned short* __restrict__ h4, unsigned short* __restrict__ l4) {
    int k = blockIdx.x, n = threadIdx.x;      // 512 x 512, y selects matrix
    const float* W = (blockIdx.y == 0) ? W2 : (blockIdx.y == 1) ? W3 : W4;
    unsigned short* hi = (blockIdx.y == 0) ? h2 : (blockIdx.y == 1) ? h3 : h4;
    unsigned short* lo = (blockIdx.y == 0) ? l2 : (blockIdx.y == 1) ? l3 : l4;
    float v = W[(size_t)k * G + n];
    __nv_bfloat16 h = __float2bfloat16_rn(v);
    float hf = __bfloat162float(h);
    __nv_bfloat16 l = __float2bfloat16_rn(v - hf);
    hi[(size_t)n * G + k] = __bfloat16_as_ushort(h);
    lo[(size_t)n * G + k] = __bfloat16_as_ushort(l);
}

// ---- main tcgen05 GEMM: cg2 pair tile 256x256, 4-stage ring ----------------
// MODE 0: A built by warps 3-15 from relu(Ai+Bj+Cq); B via TMA
// MODE 1: A and B via TMA; MODE 2: same + fused mean epilogue
template<int MODE>
__global__ __launch_bounds__(THREADS, 1) __cluster_dims__(2, 1, 1)
void k_mma(const __grid_constant__ CUtensorMap tmAh,
           const __grid_constant__ CUtensorMap tmAl,
           const __grid_constant__ CUtensorMap tmBh,
           const __grid_constant__ CUtensorMap tmBl,
           const float* __restrict__ bias,
           unsigned short* __restrict__ oHi, unsigned short* __restrict__ oLo,
           const unsigned short* __restrict__ aHi, const unsigned short* __restrict__ aLo,
           const unsigned short* __restrict__ wHi, const unsigned short* __restrict__ wLo) {
    extern __shared__ char smem[];
#if TC_OK
    const uint32_t sbase = smem_u32(smem);
    const int tid  = threadIdx.x;
    const int wid  = tid >> 5;
    const int lane = tid & 31;
    const int pair = blockIdx.x >> 1;         // 0..1023
    const uint32_t rank = ctarank();          // 0/1
    const int nBase = blockIdx.y * BN;        // 0 or 256
    const int rowBase = pair * BMP + (int)rank * BMC;
    float* sBias = (float*)(smem + S_BIAS);

    const unsigned fullCnt = (MODE == 0) ? 14u : 1u;   // 13 builder warps + expect_tx
    const unsigned txBytes = (MODE == 0) ? 16384u : 32768u;

    if (wid == 0) { TC_ALLOC2(sbase + S_TMEM_O, 256); TC_RELINQ2(); }
    if (tid == 0) {
        #pragma unroll
        for (int b = 0; b < NSTAGE; ++b) {
            MBAR_INIT(sbase + S_FULL(b), fullCnt);
            MBAR_INIT(sbase + S_FREE(b), 1);
            MBAR_INIT(sbase + S_R1RD(b), 1);
        }
        MBAR_INIT(sbase + S_DONE, 1);
    }
    if (tid < BN) sBias[tid] = bias[nBase + tid];
    __syncthreads();
    CLUSTER_SYNC();                                    // all mbarriers live
    uint32_t tmem;
    asm volatile("ld.shared.b32 %0, [%1];" : "=r"(tmem) : "r"(sbase + S_TMEM_O));

    if (wid == 1) {
        if (elect_one()) {
            // ============ TMA producer (1 thread per CTA; local tiles) ======
            for (int t = 0; t < TITER; ++t) {
                const int b = t % NSTAGE, kB = t * BK;
                if (t >= NSTAGE) mbar_wait(sbase + S_FREE(b), ((t - NSTAGE) / NSTAGE) & 1);
                MBAR_EXPECT_TX(sbase + S_FULL(b), txBytes);
                if (MODE != 0) {
                    TMA2D(sbase + ST_A_HI(b), &tmAh, kB, rowBase, sbase + S_FULL(b));
                    TMA2D(sbase + ST_A_LO(b), &tmAl, kB, rowBase, sbase + S_FULL(b));
                }
                TMA2D(sbase + ST_B_HI(b), &tmBh, kB, nBase + (int)rank * 128, sbase + S_FULL(b));
                TMA2D(sbase + ST_B_LO(b), &tmBl, kB, nBase + (int)rank * 128, sbase + S_FULL(b));
            }
        }
    } else if (wid == 2) {
        // ============ rank-1 watcher: forward local FULL to leader ==========
        if (rank == 1 && elect_one()) {
            for (int t = 0; t < TITER; ++t) {
                const int b = t % NSTAGE;
                mbar_wait(sbase + S_FULL(b), (t / NSTAGE) & 1);
                MBAR_ARRIVE_LEADER(sbase + S_R1RD(b));
            }
        }
    } else if (MODE == 0 && wid >= 3) {
        // ============ A-tile builders (warps 3-15, 416 thr, 128 rows) =======
        const int lt = tid - 96;
        for (int t = 0; t < TITER; ++t) {
            const int b = t % NSTAGE, kB = t * BK;
            if (t >= NSTAGE) mbar_wait(sbase + S_FREE(b), ((t - NSTAGE) / NSTAGE) & 1);
            for (int idx = lt; idx < 512; idx += 416) {
                int r = idx >> 2, u = idx & 3;
                int gr = rowBase + r;
                int n = gr >> 12, i = (gr >> 6) & 63, j = gr & 63;
                size_t oA = ((size_t)(n * 64 + i)) * G + kB + u * 8;
                size_t oB = ((size_t)(n * 64 + j)) * G + kB + u * 8;
                size_t oQ = (size_t)n * G + kB + u * 8;
                unsigned hw[4], lw[4];
                #pragma unroll
                for (int hh = 0; hh < 2; ++hh) {
                    float4 a4 = *(const float4*)&g_Ai[oA + hh * 4];
                    float4 b4 = *(const float4*)&g_Bj[oB + hh * 4];
                    float4 q4 = *(const float4*)&g_Cq[oQ + hh * 4];
                    float v0 = fmaxf(a4.x + b4.x + q4.x, 0.f);
                    float v1 = fmaxf(a4.y + b4.y + q4.y, 0.f);
                    float v2 = fmaxf(a4.z + b4.z + q4.z, 0.f);
                    float v3 = fmaxf(a4.w + b4.w + q4.w, 0.f);
                    split2t(v0, v1, hw[hh*2],   lw[hh*2]);
                    split2t(v2, v3, hw[hh*2+1], lw[hh*2+1]);
                }
                unsigned off = SWZ64((unsigned)(r * 64 + u * 16));
                *(uint4*)(smem + ST_A_HI(b) + off) = make_uint4(hw[0],hw[1],hw[2],hw[3]);
                *(uint4*)(smem + ST_A_LO(b) + off) = make_uint4(lw[0],lw[1],lw[2],lw[3]);
            }
            FENCE_ASYNC();
            __syncwarp();
            if (elect_one()) MBAR_ARRIVE(sbase + S_FULL(b));
        }
    } else if (wid == 0) {
        // ============ MMA issuer (rank 0 only, 1 thread) ====================
        if (rank == 0 && elect_one()) {
            for (int t = 0; t < TITER; ++t) {
                const int b = t % NSTAGE;
                const uint32_t par = (t / NSTAGE) & 1;
                mbar_wait(sbase + S_FULL(b), par);       // local tiles ready
                mbar_wait_clu(sbase + S_R1RD(b), par);   // peer tiles ready
                uint64_t adH = MAKE_DESC64(sbase + ST_A_HI(b));
                uint64_t adL = MAKE_DESC64(sbase + ST_A_LO(b));
                uint64_t bdH = MAKE_DESC64(sbase + ST_B_HI(b));
                uint64_t bdL = MAKE_DESC64(sbase + ST_B_LO(b));
                #pragma unroll
                for (int s = 0; s < 2; ++s) {            // two K=16 chunks
                    uint64_t o = (uint64_t)(s * 2);
                    uint32_t en = ((t | s) != 0) ? 1u : 0u;
                    mma_bf16_ss_cg2(tmem, adH + o, bdH + o, MMA_IDESC, en);
                    mma_bf16_ss_cg2(tmem, adH + o, bdL + o, MMA_IDESC, 1u);
                    mma_bf16_ss_cg2(tmem, adL + o, bdH + o, MMA_IDESC, 1u);
                }
                TC_COMMIT_MC2(sbase + S_FREE(b), 0x3);
            }
            TC_COMMIT_MC2(sbase + S_DONE, 0x3);
        }
    }

    // all threads (both CTAs) wait for the final MMA
    mbar_wait(sbase + S_DONE, 0);
    TC_FENCE_AFTER();

    // ---- epilogue: 8 warps read this CTA's D (128 rows x 256 cols) ---------
    float* sPart = (float*)(smem + ST_A_HI(0));   // [4][256] for MODE 2
    if (wid < 8) {
        const int grp = wid >> 2;                 // col half 0/1
        const int sub = wid & 3;                  // lane block
        size_t grow = (size_t)rowBase + sub * 32 + lane;
        #pragma unroll 1
        for (int cp = 0; cp < 2; ++cp) {
            uint32_t rA[32], rB[32];
            int cc0 = grp * 128 + cp * 64;
            TC_LD_X32(rA, tmem + cc0);
            TC_LD_X32(rB, tmem + cc0 + 32);
            TC_WAIT_LD();
            #pragma unroll
            for (int hh = 0; hh < 2; ++hh) {
                uint32_t* r = hh ? rB : rA;
                int cc = cc0 + hh * 32;
                if (MODE < 2) {
                    #pragma unroll
                    for (int q = 0; q < 4; ++q) {
                        unsigned hw[4], lw[4];
                        #pragma unroll
                        for (int e = 0; e < 4; ++e) {
                            float v0 = fmaxf(__uint_as_float(r[q*8+e*2])   + sBias[cc+q*8+e*2],   0.f);
                            float v1 = fmaxf(__uint_as_float(r[q*8+e*2+1]) + sBias[cc+q*8+e*2+1], 0.f);
                            split2t(v0, v1, hw[e], lw[e]);
                        }
                        size_t go = grow * G + nBase + cc + q * 8;
                        *(uint4*)&oHi[go] = make_uint4(hw[0], hw[1], hw[2], hw[3]);
                        *(uint4*)&oLo[go] = make_uint4(lw[0], lw[1], lw[2], lw[3]);
                    }
                } else {
                    #pragma unroll
                    for (int j = 0; j < 32; ++j) {
                        float v = fmaxf(__uint_as_float(r[j]) + sBias[cc + j], 0.f);
                        #pragma unroll
                        for (int o = 16; o > 0; o >>= 1)
                            v += __shfl_xor_sync(0xFFFFFFFFu, v, o);
                        if (lane == 0) sPart[sub * 256 + cc + j] = v;
                    }
                }
            }
        }
    }
    __syncthreads();
    if (MODE == 2 && tid < BN) {
        float s = sPart[tid] + sPart[256 + tid] + sPart[512 + tid] + sPart[768 + tid];
        g_part[(size_t)blockIdx.x * G + nBase + tid] = s;
    }
    __syncthreads();
    if (tid == 0) {
        #pragma unroll
        for (int b = 0; b < NSTAGE; ++b) {
            MBAR_INVAL(sbase + S_FULL(b)); MBAR_INVAL(sbase + S_FREE(b));
            MBAR_INVAL(sbase + S_R1RD(b));
        }
        MBAR_INVAL(sbase + S_DONE);
    }
    __syncthreads();
    if (wid == 0) TC_DEALLOC2(tmem, 256);
    CLUSTER_SYNC();
#else
    // -------- scalar fallback (non-sm_103a compile passes only) --------
    const int tid  = threadIdx.x;
    const int pair = blockIdx.x >> 1;
    const int rnk  = blockIdx.x & 1;
    const int nBase = blockIdx.y * BN;
    if (tid >= BN) return;
    const int col = nBase + tid;
    float colsum = 0.f;
    for (int r = 0; r < BMC; ++r) {
        size_t gr = (size_t)pair * BMP + rnk * BMC + r;
        float acc = bias[col];
        int n = (int)(gr >> 12), i = ((int)gr >> 6) & 63, j = (int)gr & 63;
        for (int k = 0; k < G; ++k) {
            float a;
            if (MODE == 0) {
                float raw = fmaxf(g_Ai[((size_t)(n * 64 + i)) * G + k]
                                + g_Bj[((size_t)(n * 64 + j)) * G + k]
                                + g_Cq[(size_t)n * G + k], 0.f);
                unsigned hh, ll;
                split2t(raw, 0.f, hh, ll);
                a = us2f((unsigned short)(hh & 0xFFFFu)) + us2f((unsigned short)(ll & 0xFFFFu));
            } else {
                a = us2f(aHi[gr * G + k]) + us2f(aLo[gr * G + k]);
            }
            float w = us2f(wHi[(size_t)col * G + k]) + us2f(wLo[(size_t)col * G + k]);
            acc = fmaf(a, w, acc);
        }
        float v = fmaxf(acc, 0.f);
        if (MODE < 2) {
            unsigned hh, ll;
            split2t(v, 0.f, hh, ll);
            oHi[gr * G + col] = (unsigned short)(hh & 0xFFFFu);
            oLo[gr * G + col] = (unsigned short)(ll & 0xFFFFu);
        } else colsum += v;
    }
    if (MODE == 2) g_part[(size_t)blockIdx.x * G + col] = colsum;
#endif
}

// ---- final mean over 4096 pairs (32 CTA partials per image) ----------------
__global__ void k_reduce2() {
    int n = blockIdx.x, k = threadIdx.x;   // 64 x 512
    float s = 0.f;
    #pragma unroll
    for (int b = 0; b < 32; ++b)
        s += g_part[(size_t)(n * 32 + b) * G + k];
    g_ctx[n * G + k] = s * (1.0f / 4096.0f);
}

// ---- f-MLP + log_softmax ---------------------------------------------------
__global__ void k_fmlp(const float* __restrict__ fw1, const float* __restrict__ fb1,
                       const float* __restrict__ fw2, const float* __restrict__ fb2,
                       const float* __restrict__ fw3, const float* __restrict__ fb3,
                       float* __restrict__ out) {
    int n = blockIdx.x, tid = threadIdx.x;   // 512 threads
    __shared__ float x[G], y[G];
    __shared__ float sc[2];
    x[tid] = g_ctx[n * G + tid];
    __syncthreads();
    float s0 = fb1[tid], s1 = 0.f;
    #pragma unroll 8
    for (int c = 0; c < G; c += 2) {
        s0 = fmaf(x[c],     fw1[(size_t)c * G + tid], s0);
        s1 = fmaf(x[c + 1], fw1[(size_t)(c + 1) * G + tid], s1);
    }
    y[tid] = fmaxf(s0 + s1, 0.f);
    __syncthreads();
    s0 = fb2[tid]; s1 = 0.f;
    #pragma unroll 8
    for (int c = 0; c < G; c += 2) {
        s0 = fmaf(y[c],     fw2[(size_t)c * G + tid], s0);
        s1 = fmaf(y[c + 1], fw2[(size_t)(c + 1) * G + tid], s1);
    }
    x[tid] = fmaxf(s0 + s1, 0.f);
    __syncthreads();
    if (tid < 2) {
        float t = fb3[tid];
        for (int c = 0; c < G; ++c) t = fmaf(x[c], fw3[c * 2 + tid], t);
        sc[tid] = t;
    }
    __syncthreads();
    if (tid == 0) {
        float m = fmaxf(sc[0], sc[1]);
        float lse = m + logf(expf(sc[0] - m) + expf(sc[1] - m));
        out[n * 2 + 0] = sc[0] - lse;
        out[n * 2 + 1] = sc[1] - lse;
    }
}

// ---------------- host: tensormap building ----------------
typedef CUresult (*EncodeFn)(CUtensorMap*, CUtensorMapDataType, cuuint32_t, void*,
                             const cuuint64_t*, const cuuint64_t*, const cuuint32_t*,
                             const cuuint32_t*, CUtensorMapInterleave, CUtensorMapSwizzle,
                             CUtensorMapL2promotion, CUtensorMapFloatOOBfill);

static EncodeFn get_encoder() {
    void* fn = nullptr;
    cudaDriverEntryPointQueryResult st;
    cudaGetDriverEntryPoint("cuTensorMapEncodeTiled", &fn, cudaEnableDefault, &st);
    return (EncodeFn)fn;
}
static void build_map(EncodeFn enc, CUtensorMap* m, void* base,
                      unsigned long long rows, unsigned boxRows) {
    cuuint64_t dims[2]    = {(cuuint64_t)G, (cuuint64_t)rows};
    cuuint64_t strides[1] = {(cuuint64_t)G * 2};   // bf16 bytes
    cuuint32_t box[2]     = {(cuuint32_t)BK, (cuuint32_t)boxRows};
    cuuint32_t es[2]      = {1, 1};
    enc(m, CU_TENSOR_MAP_DATA_TYPE_BFLOAT16, 2, base, dims, strides, box, es,
        CU_TENSOR_MAP_INTERLEAVE_NONE, CU_TENSOR_MAP_SWIZZLE_64B,
        CU_TENSOR_MAP_L2_PROMOTION_L2_128B, CU_TENSOR_MAP_FLOAT_OOB_FILL_NONE);
}

// ----------------------------------------------------------------------------
extern "C" void kernel_launch(void* const* d_in, const int* in_sizes, int n_in,
                              void* d_out, int out_size) {
    const float* img  = (const float*)d_in[0];
    const float* ques = (const float*)d_in[1];
    const float* g_w1 = (const float*)d_in[2];
    const float* g_b1 = (const float*)d_in[3];
    const float* g_w2 = (const float*)d_in[4];
    const float* g_b2 = (const float*)d_in[5];
    const float* g_w3 = (const float*)d_in[6];
    const float* g_b3 = (const float*)d_in[7];
    const float* g_w4 = (const float*)d_in[8];
    const float* g_b4 = (const float*)d_in[9];
    const float* f_w1 = (const float*)d_in[10];
    const float* f_b1 = (const float*)d_in[11];
    const float* f_w2 = (const float*)d_in[12];
    const float* f_b2 = (const float*)d_in[13];
    const float* f_w3 = (const float*)d_in[14];
    const float* f_b3 = (const float*)d_in[15];
    float* out = (float*)d_out;

    cudaFuncSetAttribute(k_mma<0>, cudaFuncAttributeMaxDynamicSharedMemorySize, SMEM_SZ);
    cudaFuncSetAttribute(k_mma<1>, cudaFuncAttributeMaxDynamicSharedMemorySize, SMEM_SZ);
    cudaFuncSetAttribute(k_mma<2>, cudaFuncAttributeMaxDynamicSharedMemorySize, SMEM_SZ);

    unsigned short *w2h, *w2l, *w3h, *w3l, *w4h, *w4l, *h2h, *h2l, *h3h, *h3l;
    cudaGetSymbolAddress((void**)&w2h, g_w2h); cudaGetSymbolAddress((void**)&w2l, g_w2l);
    cudaGetSymbolAddress((void**)&w3h, g_w3h); cudaGetSymbolAddress((void**)&w3l, g_w3l);
    cudaGetSymbolAddress((void**)&w4h, g_w4h); cudaGetSymbolAddress((void**)&w4l, g_w4l);
    cudaGetSymbolAddress((void**)&h2h, g_h2h); cudaGetSymbolAddress((void**)&h2l, g_h2l);
    cudaGetSymbolAddress((void**)&h3h, g_h3h); cudaGetSymbolAddress((void**)&h3l, g_h3l);

    EncodeFn enc = get_encoder();
    CUtensorMap mW2h, mW2l, mW3h, mW3l, mW4h, mW4l, mA2h, mA2l, mA3h, mA3l;
    build_map(enc, &mW2h, w2h, G, 128);      build_map(enc, &mW2l, w2l, G, 128);
    build_map(enc, &mW3h, w3h, G, 128);      build_map(enc, &mW3l, w3l, G, 128);
    build_map(enc, &mW4h, w4h, G, 128);      build_map(enc, &mW4l, w4l, G, 128);
    build_map(enc, &mA2h, h2h, MROWS, 128);  build_map(enc, &mA2l, h2l, MROWS, 128);
    build_map(enc, &mA3h, h3h, MROWS, 128);  build_map(enc, &mA3l, h3l, MROWS, 128);

    k_wprep3<<<dim3(G, 3), G>>>(g_w2, g_w3, g_w4, w2h, w2l, w3h, w3l, w4h, w4l);
    k_ab<<<dim3(NB, 8), 512>>>(img, g_w1);
    k_cq<<<NB, 512>>>(ques, g_w1, g_b1);

    dim3 gg(NCTAX, G / BN);   // 2048 x 2, clusters of 2 along x
    k_mma<0><<<gg, THREADS, SMEM_SZ>>>(mW2h, mW2l, mW2h, mW2l, g_b2, h2h, h2l,
                                       nullptr, nullptr, w2h, w2l);
    k_mma<1><<<gg, THREADS, SMEM_SZ>>>(mA2h, mA2l, mW3h, mW3l, g_b3, h3h, h3l,
                                       h2h, h2l, w3h, w3l);
    k_mma<2><<<gg, THREADS, SMEM_SZ>>>(mA3h, mA3l, mW4h, mW4l, g_b4, nullptr, nullptr,
                                       h3h, h3l, w4h, w4l);

    k_reduce2<<<NB, 512>>>();
    k_fmlp<<<NB, 512>>>(f_w1, f_b1, f_w2, f_b2, f_w3, f_b3, out);
}